// round 17
// baseline (speedup 1.0000x reference)
#include <cuda_runtime.h>
#include <cstdint>

#define KDIM 4096
#define NDIM 4096
#define MDIM 8192
#define KT 128
#define KITERS (KDIM / KT)      // 32
#define MT 128
#define NT 128
#define THREADS 256
#define STRIDE 144              // 128B row + 16B pad; banks: 36*grp+qid covers 32
#define A_TILE (MT * STRIDE)    // 18432
#define STAGE_BYTES (2 * A_TILE)  // 36864
#define STAGES 3
#define SMEM_TOTAL (STAGES * STAGE_BYTES)  // 110592

// legal scratch
__device__ int8_t gXq[(size_t)MDIM * KDIM];
__device__ int8_t gWt[(size_t)NDIM * KDIM];   // W transposed: [N][K], K-major

__device__ __forceinline__ uint32_t pack4i(int4 v) {
    return (uint32_t)(uint8_t)(int8_t)v.x | ((uint32_t)(uint8_t)(int8_t)v.y << 8) |
           ((uint32_t)(uint8_t)(int8_t)v.z << 16) | ((uint32_t)(uint8_t)(int8_t)v.w << 24);
}

#define XN16 ((MDIM * KDIM) / 16)   // 2097152
#define XBLOCKS (XN16 / 256)        // 8192
#define TBLOCKS 1024

// Merged pre-pass: blocks [0, XBLOCKS) pack X; blocks [XBLOCKS, +TBLOCKS) transpose W.
__global__ void __launch_bounds__(256)
prep_kernel(const int4* __restrict__ x, const int* __restrict__ w,
            uint4* __restrict__ xq, int8_t* __restrict__ wt)
{
    const int tid = threadIdx.x;
    if (blockIdx.x < XBLOCKS) {
        int idx = blockIdx.x * 256 + tid;
        const int4* s = x + (size_t)idx * 4;
        uint4 out;
        out.x = pack4i(s[0]); out.y = pack4i(s[1]);
        out.z = pack4i(s[2]); out.w = pack4i(s[3]);
        xq[idx] = out;
    } else {
        const int blk = blockIdx.x - XBLOCKS;
        const int bk = blk & 31;
        const int bn = blk >> 5;
        const int k0 = bk * 128, n0 = bn * 128;
        const int kg = tid & 7;
        const int ng = tid >> 3;
#pragma unroll
        for (int band = 0; band < 4; band++) {
            const int k = k0 + band * 32 + kg * 4;
            const int n = n0 + ng * 4;
            uint32_t p[4];
#pragma unroll
            for (int j = 0; j < 4; j++)
                p[j] = pack4i(*reinterpret_cast<const int4*>(w + (size_t)(k + j) * NDIM + n));
            uint32_t t0 = __byte_perm(p[0], p[1], 0x5140);
            uint32_t t1 = __byte_perm(p[0], p[1], 0x7362);
            uint32_t t2 = __byte_perm(p[2], p[3], 0x5140);
            uint32_t t3 = __byte_perm(p[2], p[3], 0x7362);
            *reinterpret_cast<uint32_t*>(wt + (size_t)(n + 0) * KDIM + k) = __byte_perm(t0, t2, 0x5410);
            *reinterpret_cast<uint32_t*>(wt + (size_t)(n + 1) * KDIM + k) = __byte_perm(t0, t2, 0x7632);
            *reinterpret_cast<uint32_t*>(wt + (size_t)(n + 2) * KDIM + k) = __byte_perm(t1, t3, 0x5410);
            *reinterpret_cast<uint32_t*>(wt + (size_t)(n + 3) * KDIM + k) = __byte_perm(t1, t3, 0x7632);
        }
    }
}

// ---------------- GEMM ----------------
__device__ __forceinline__ void mma_s8(int* d, const uint32_t* a, const uint32_t* b) {
    asm volatile(
        "mma.sync.aligned.m16n8k32.row.col.s32.s8.s8.s32 "
        "{%0,%1,%2,%3}, {%4,%5,%6,%7}, {%8,%9}, {%0,%1,%2,%3};"
        : "+r"(d[0]), "+r"(d[1]), "+r"(d[2]), "+r"(d[3])
        : "r"(a[0]), "r"(a[1]), "r"(a[2]), "r"(a[3]), "r"(b[0]), "r"(b[1]));
}

__device__ __forceinline__ float quantf(int acc, float asc, float bsc) {
    float f = (float)acc * asc;
    f = f * bsc;
    int v = __float2int_rn(f);    // half-even == jnp.round
    return (float)max(-128, min(127, v));
}

__device__ __forceinline__ void cp16(uint32_t dst, const void* src) {
    asm volatile("cp.async.cg.shared.global [%0], [%1], 16;"
                 :: "r"(dst), "l"(src));
}

__global__ void __launch_bounds__(THREADS, 2)
w8a8_imma_kernel(const float* __restrict__ Af, const float* __restrict__ Bf,
                 float* __restrict__ Out)
{
    extern __shared__ __align__(16) char sm[];
    const uint32_t smem_base = (uint32_t)__cvta_generic_to_shared(sm);

    const int tid  = threadIdx.x;
    const int lane = tid & 31;
    const int wid  = tid >> 5;
    const int grp  = lane >> 2;
    const int qid  = lane & 3;

    const int m0 = (int)(blockIdx.x >> 5) * MT;
    const int n0 = (int)(blockIdx.x & 31) * NT;

    const float asc = Af[0];

    // copy mapping: row = tid>>1, 64B half = (tid&1)*64; 4 cp16 each for A and B
    const int crow = tid >> 1;
    const int chc  = (tid & 1) * 64;
    const int8_t* srcA = gXq + (size_t)(m0 + crow) * KDIM + chc;
    const int8_t* srcB = gWt + (size_t)(n0 + crow) * KDIM + chc;
    const uint32_t dstA = smem_base + crow * STRIDE + chc;
    const uint32_t dstB = dstA + A_TILE;

#define ISSUE(stage, it)                                                      \
    {                                                                         \
        const uint32_t so = (stage) * STAGE_BYTES;                            \
        const int8_t* a_ = srcA + (size_t)(it) * KT;                          \
        const int8_t* b_ = srcB + (size_t)(it) * KT;                          \
        cp16(dstA + so,      a_);                                             \
        cp16(dstA + so + 16, a_ + 16);                                        \
        cp16(dstA + so + 32, a_ + 32);                                        \
        cp16(dstA + so + 48, a_ + 48);                                        \
        cp16(dstB + so,      b_);                                             \
        cp16(dstB + so + 16, b_ + 16);                                        \
        cp16(dstB + so + 32, b_ + 32);                                        \
        cp16(dstB + so + 48, b_ + 48);                                        \
        asm volatile("cp.async.commit_group;" ::: "memory");                  \
    }

    const int mw = (wid >> 1) * 32;
    const int nw = (wid & 1) * 64;

    int acc[2][8][4];
#pragma unroll
    for (int mt = 0; mt < 2; mt++)
#pragma unroll
        for (int nt = 0; nt < 8; nt++)
#pragma unroll
            for (int r = 0; r < 4; r++) acc[mt][nt][r] = 0;

    // prologue: fill stages 0..STAGES-2
    ISSUE(0, 0);
    ISSUE(1, 1);

#pragma unroll 1
    for (int it = 0; it < KITERS; it++) {
        const int cur = it % STAGES;

        asm volatile("cp.async.wait_group %0;" :: "n"(STAGES - 2) : "memory");
        __syncthreads();
        // Safe: barrier guarantees all warps finished compute(it-1); the stage
        // written here ((it+2)%3) was last read at iter it-1.
        if (it + STAGES - 1 < KITERS)
            ISSUE((it + STAGES - 1) % STAGES, it + STAGES - 1);

        const char* Ab = sm + cur * STAGE_BYTES;
        const char* Bb = Ab + A_TILE;

#pragma unroll
        for (int kstep = 0; kstep < 4; kstep++) {
            uint32_t a[2][4];
#pragma unroll
            for (int mt = 0; mt < 2; mt++) {
                const char* p = Ab + (mw + mt * 16 + grp) * STRIDE +
                                kstep * 32 + qid * 4;
                a[mt][0] = *reinterpret_cast<const uint32_t*>(p);
                a[mt][1] = *reinterpret_cast<const uint32_t*>(p + 8 * STRIDE);
                a[mt][2] = *reinterpret_cast<const uint32_t*>(p + 16);
                a[mt][3] = *reinterpret_cast<const uint32_t*>(p + 8 * STRIDE + 16);
            }
            uint32_t b[8][2];
#pragma unroll
            for (int nt = 0; nt < 8; nt++) {
                const char* p = Bb + (nw + nt * 8 + grp) * STRIDE +
                                kstep * 32 + qid * 4;
                b[nt][0] = *reinterpret_cast<const uint32_t*>(p);
                b[nt][1] = *reinterpret_cast<const uint32_t*>(p + 16);
            }
#pragma unroll
            for (int mt = 0; mt < 2; mt++)
#pragma unroll
                for (int nt = 0; nt < 8; nt++)
                    mma_s8(acc[mt][nt], a[mt], b[nt]);
        }
        // no trailing barrier: next iter's top barrier provides the ordering
    }

    // ---------------- Epilogue: float32 output ----------------
#pragma unroll
    for (int mt = 0; mt < 2; mt++) {
        const int r0 = m0 + mw + mt * 16 + grp;
#pragma unroll
        for (int nt = 0; nt < 8; nt++) {
            const int col = n0 + nw + nt * 8 + qid * 2;
            const float2 bb = *reinterpret_cast<const float2*>(Bf + col);
            const int* v = acc[mt][nt];
            float2 lo = make_float2(quantf(v[0], asc, bb.x), quantf(v[1], asc, bb.y));
            float2 hi = make_float2(quantf(v[2], asc, bb.x), quantf(v[3], asc, bb.y));
            *reinterpret_cast<float2*>(Out + (size_t)r0 * NDIM + col) = lo;
            *reinterpret_cast<float2*>(Out + (size_t)(r0 + 8) * NDIM + col) = hi;
        }
    }
}

extern "C" void kernel_launch(void* const* d_in, const int* in_sizes, int n_in,
                              void* d_out, int out_size)
{
    // Measured (R10): positional x, weight, a, b; x/w int32, a/b f32, out f32.
    const int4*  X  = (const int4*)d_in[0];
    const int*   W  = (const int*)d_in[1];
    const float* Af = (const float*)d_in[2];
    const float* Bf = (const float*)d_in[3];
    float* Out = (float*)d_out;

    uint4*  xq; cudaGetSymbolAddress((void**)&xq, gXq);
    int8_t* wt; cudaGetSymbolAddress((void**)&wt, gWt);

    prep_kernel<<<XBLOCKS + TBLOCKS, 256>>>(X, W, xq, wt);

    cudaFuncSetAttribute(w8a8_imma_kernel,
                         cudaFuncAttributeMaxDynamicSharedMemorySize, SMEM_TOTAL);

    const int grid = (MDIM / MT) * (NDIM / NT);  // 64 * 32 = 2048
    w8a8_imma_kernel<<<grid, THREADS, SMEM_TOTAL>>>(Af, Bf, Out);
}